// round 15
// baseline (speedup 1.0000x reference)
#include <cuda_runtime.h>
#include <cstdint>
#include <math.h>

#define BB 8
#define CC 256
#define HH 96
#define WW 128
#define HWSZ (HH*WW)
#define RD 4
#define ND 9

#define HQB 8
#define WT 16
#define NB 24
#define KC 8
#define NSTG (CC/KC)      // 32
#define APITCH 12
#define BPITCH 12
#define NTHREADS 256

#define SA_STG (16*16*APITCH)          // 3072 floats per buffer
#define SB_OFF (2*SA_STG)              // 6144
#define SB_STG (HQB*NB*BPITCH)         // 2304
#define SINVA_OFF (SB_OFF + 2*SB_STG)  // 10752
#define SINVB_OFF (SINVA_OFF + 256)
#define SMEM_FLOATS (SINVB_OFF + HQB*NB)
#define SMEM_BYTES (SMEM_FLOATS*4)

typedef unsigned int u32;

__device__ __forceinline__ unsigned smem_u32(const void* p) {
    return (unsigned)__cvta_generic_to_shared(p);
}
__device__ __forceinline__ u32 cvt_tf32(float v) {
    u32 r; asm("cvt.rna.tf32.f32 %0, %1;" : "=r"(r) : "f"(v)); return r;
}
__device__ __forceinline__ void mma_tf32(float c[4], const u32 a[4], const u32 b[2]) {
    asm volatile(
        "mma.sync.aligned.m16n8k8.row.col.f32.tf32.tf32.f32 "
        "{%0,%1,%2,%3}, {%4,%5,%6,%7}, {%8,%9}, {%0,%1,%2,%3};"
        : "+f"(c[0]), "+f"(c[1]), "+f"(c[2]), "+f"(c[3])
        : "r"(a[0]), "r"(a[1]), "r"(a[2]), "r"(a[3]), "r"(b[0]), "r"(b[1]));
}
__device__ __forceinline__ void ldm_x4(u32 r[4], unsigned addr) {
    asm volatile("ldmatrix.sync.aligned.m8n8.x4.shared.b16 {%0,%1,%2,%3}, [%4];"
                 : "=r"(r[0]), "=r"(r[1]), "=r"(r[2]), "=r"(r[3]) : "r"(addr));
}
__device__ __forceinline__ void ldm_x2(u32 r[2], unsigned addr) {
    asm volatile("ldmatrix.sync.aligned.m8n8.x2.shared.b16 {%0,%1}, [%2];"
                 : "=r"(r[0]), "=r"(r[1]) : "r"(addr));
}

__global__ __launch_bounds__(NTHREADS, 1)
void corr_mma_kernel(const float* __restrict__ fr, const float* __restrict__ fq,
                     float* __restrict__ out) {
    extern __shared__ float sm[];
    const int tid  = threadIdx.x;
    const int wid  = tid >> 5;
    const int lane = tid & 31;

    const int b   = blockIdx.z;
    const int hq0 = blockIdx.y * HQB;
    const int w0  = blockIdx.x * WT;

    // ---- structural-zero outputs (OOB fq rows): edge CTAs only (validated R13/R14)
    {
        const int pd[10] = {0,0,0,0,1,1,1,2,2,3};
        const int ph[10] = {0,1,2,3,0,1,2,0,1,0};
        if (blockIdx.y == 0) {
            for (int idx = tid; idx < 1440; idx += NTHREADS) {
                int p = idx / 144, rem = idx % 144, dx = rem / 16, w = rem % 16;
                out[((size_t)b * 81 + pd[p] * ND + dx) * HWSZ + ph[p] * WW + w0 + w] = 0.f;
            }
        }
        if (blockIdx.y == (HH / HQB) - 1) {
            for (int idx = tid; idx < 1440; idx += NTHREADS) {
                int p = idx / 144, rem = idx % 144, dx = rem / 16, w = rem % 16;
                out[((size_t)b * 81 + (8 - pd[p]) * ND + dx) * HWSZ
                    + (HH - 1 - ph[p]) * WW + w0 + w] = 0.f;
            }
        }
    }

    // ---- A staging role: thread owns (alh, apx); 8 channels per stage
    const int apx = tid & 15;
    const int alh = tid >> 4;
    const int ah  = hq0 - 4 + alh;
    const bool av = (ah >= 0 && ah < HH);
    const float* aptr = fr + (size_t)b * CC * HWSZ + (av ? ah : 0) * WW + (w0 + apx);

    // ---- B staging role
    const int bpx = (tid < 192) ? (tid % NB) : 0;
    const int bhq = (tid < 192) ? (tid / NB) : 0;
    const int wq  = w0 - RD + bpx;
    const bool bv = (tid < 192) && (wq >= 0 && wq < WW);
    const float* bptr = fq + (size_t)b * CC * HWSZ + (hq0 + bhq) * WW + (bv ? wq : 0);

    float anrm = 0.f, bnrm = 0.f;
    float cAcc[27][4];
    #pragma unroll
    for (int i = 0; i < 27; ++i)
        #pragma unroll
        for (int j = 0; j < 4; ++j) cAcc[i][j] = 0.f;

    // two register prefetch buffers (prefetch distance 2 stages)
    float rbufA[2][KC], rbufB[2][KC];

    // pure load batch into SLOT; pointers advance (calls happen in stage order)
    #define LDGSTAGE(SLOT) do {                                              \
        _Pragma("unroll")                                                    \
        for (int kc = 0; kc < KC; ++kc)                                      \
            rbufA[SLOT][kc] = av ? aptr[(size_t)kc * HWSZ] : 0.f;            \
        _Pragma("unroll")                                                    \
        for (int kc = 0; kc < KC; ++kc)                                      \
            rbufB[SLOT][kc] = bv ? bptr[(size_t)kc * HWSZ] : 0.f;            \
        aptr += (size_t)KC * HWSZ;                                           \
        bptr += (size_t)KC * HWSZ;                                           \
    } while (0)

    // norm + cvt + store from SLOT into smem buffer BUF (data loaded 2 stages ago)
    #define STSSTAGE(SLOT, BUF) do {                                         \
        _Pragma("unroll")                                                    \
        for (int kc = 0; kc < KC; ++kc)                                      \
            anrm = fmaf(rbufA[SLOT][kc], rbufA[SLOT][kc], anrm);             \
        uint4* pa = (uint4*)(sm + (BUF) * SA_STG + (alh * 16 + apx) * APITCH);\
        pa[0] = make_uint4(cvt_tf32(rbufA[SLOT][0]), cvt_tf32(rbufA[SLOT][1]),\
                           cvt_tf32(rbufA[SLOT][2]), cvt_tf32(rbufA[SLOT][3]));\
        pa[1] = make_uint4(cvt_tf32(rbufA[SLOT][4]), cvt_tf32(rbufA[SLOT][5]),\
                           cvt_tf32(rbufA[SLOT][6]), cvt_tf32(rbufA[SLOT][7]));\
        if (tid < 192) {                                                     \
            _Pragma("unroll")                                                \
            for (int kc = 0; kc < KC; ++kc)                                  \
                bnrm = fmaf(rbufB[SLOT][kc], rbufB[SLOT][kc], bnrm);         \
            uint4* pb = (uint4*)(sm + SB_OFF + (BUF) * SB_STG                \
                                 + (bhq * NB + bpx) * BPITCH);               \
            pb[0] = make_uint4(cvt_tf32(rbufB[SLOT][0]), cvt_tf32(rbufB[SLOT][1]),\
                               cvt_tf32(rbufB[SLOT][2]), cvt_tf32(rbufB[SLOT][3]));\
            pb[1] = make_uint4(cvt_tf32(rbufB[SLOT][4]), cvt_tf32(rbufB[SLOT][5]),\
                               cvt_tf32(rbufB[SLOT][6]), cvt_tf32(rbufB[SLOT][7]));\
        }                                                                    \
    } while (0)

    // one k=8 step on smem buffer BUF (validated fragment mapping, KS removed)
    #define KSTEP(BUF) do {                                                  \
        u32 bF[3][2];                                                        \
        _Pragma("unroll")                                                    \
        for (int nt = 0; nt < 3; ++nt) {                                     \
            unsigned bd = smem_u32(sm + SB_OFF + (BUF) * SB_STG              \
                + (wid * NB + nt * 8 + (lane & 7)) * BPITCH                  \
                + (((lane >> 3) & 1) << 2));                                 \
            ldm_x2(bF[nt], bd);                                              \
        }                                                                    \
        _Pragma("unroll")                                                    \
        for (int dyt = 0; dyt < 9; ++dyt) {                                  \
            const int lh = wid + 8 - dyt;                                    \
            u32 aF[4];                                                       \
            unsigned ad = smem_u32(sm + (BUF) * SA_STG                       \
                + (lh * 16 + (lane & 15)) * APITCH + ((lane >> 4) << 2));    \
            ldm_x4(aF, ad);                                                  \
            mma_tf32(cAcc[dyt * 3 + 0], aF, bF[0]);                          \
            mma_tf32(cAcc[dyt * 3 + 1], aF, bF[1]);                          \
            mma_tf32(cAcc[dyt * 3 + 2], aF, bF[2]);                          \
        }                                                                    \
    } while (0)

    // ---- prologue: stages 0 and 1 into slots 0/1; stage0 -> smem buf0
    LDGSTAGE(0);           // stage 0 -> slot 0
    STSSTAGE(0, 0);        // exposes LDG latency once
    LDGSTAGE(1);           // stage 1 -> slot 1
    __syncthreads();

    // ---- mainloop: stage s computes buf s&1; LDG(s+2) -> slot s&1; STS(s+1) -> buf s&1^1
    #pragma unroll 1
    for (int ss = 0; ss < NSTG / 2; ++ss) {
        const int s0 = 2 * ss;
        if (s0 + 2 < NSTG) LDGSTAGE(0);   // stage s0+2 -> slot 0
        KSTEP(0);
        STSSTAGE(1, 1);                   // stage s0+1 -> smem buf1 (s0+1 <= 31 always)
        __syncthreads();
        if (s0 + 3 < NSTG) LDGSTAGE(1);   // stage s0+3 -> slot 1
        KSTEP(1);
        if (s0 + 2 < NSTG) STSSTAGE(0, 0);
        __syncthreads();
    }

    // ---- norms to smem
    sm[SINVA_OFF + alh * 16 + apx] = 1.0f / fmaxf(sqrtf(anrm), 1e-12f);
    if (tid < 192)
        sm[SINVB_OFF + bhq * NB + bpx] = 1.0f / fmaxf(sqrtf(bnrm), 1e-12f);
    __syncthreads();

    // ---- epilogue (validated mapping)
    const float scale = 1.0f / (float)CC;
    const int r1 = lane >> 2;
    const int colb = 2 * (lane & 3);

    #pragma unroll
    for (int dyt = 0; dyt < 9; ++dyt) {
        const int h = hq0 + wid + 4 - dyt;
        if (h < 0 || h >= HH) continue;
        const int lh = wid + 8 - dyt;
        const float ia1 = sm[SINVA_OFF + lh * 16 + r1] * scale;
        const float ia2 = sm[SINVA_OFF + lh * 16 + r1 + 8] * scale;
        #pragma unroll
        for (int nt = 0; nt < 3; ++nt) {
            const int col0 = nt * 8 + colb;
            const float ib0 = sm[SINVB_OFF + wid * NB + col0];
            const float ib1 = sm[SINVB_OFF + wid * NB + col0 + 1];
            const float* cf = cAcc[dyt * 3 + nt];
            int dx;
            size_t pbase = ((size_t)b * 81 + dyt * ND) * HWSZ + h * WW + w0;
            dx = col0 - r1;
            if (dx >= 0 && dx < ND) out[pbase + (size_t)dx * HWSZ + r1] = cf[0] * ia1 * ib0;
            dx = col0 + 1 - r1;
            if (dx >= 0 && dx < ND) out[pbase + (size_t)dx * HWSZ + r1] = cf[1] * ia1 * ib1;
            dx = col0 - (r1 + 8);
            if (dx >= 0 && dx < ND) out[pbase + (size_t)dx * HWSZ + r1 + 8] = cf[2] * ia2 * ib0;
            dx = col0 + 1 - (r1 + 8);
            if (dx >= 0 && dx < ND) out[pbase + (size_t)dx * HWSZ + r1 + 8] = cf[3] * ia2 * ib1;
        }
    }
    #undef LDGSTAGE
    #undef STSSTAGE
    #undef KSTEP
}

extern "C" void kernel_launch(void* const* d_in, const int* in_sizes, int n_in,
                              void* d_out, int out_size) {
    const float* fr = (const float*)d_in[0];
    const float* fq = (const float*)d_in[1];
    float* out = (float*)d_out;
    (void)in_sizes; (void)n_in; (void)out_size;

    cudaFuncSetAttribute(corr_mma_kernel,
                         cudaFuncAttributeMaxDynamicSharedMemorySize, SMEM_BYTES);

    dim3 grid(WW / WT, HH / HQB, BB);   // (8, 12, 8) = 768 CTAs
    corr_mma_kernel<<<grid, NTHREADS, SMEM_BYTES>>>(fr, fq, out);
}

// round 16
// speedup vs baseline: 1.2714x; 1.2714x over previous
#include <cuda_runtime.h>
#include <cstdint>
#include <math.h>

#define BB 8
#define CC 256
#define HH 96
#define WW 128
#define HWSZ (HH*WW)
#define RD 4
#define ND 9

#define HQB 8
#define WT 16
#define NB 24
#define KC 16
#define NSTG (CC/KC)      // 16
#define APITCH 20
#define BPITCH 20
#define NTHREADS 256

#define SA_STG (16*16*APITCH)          // 5120 floats per buffer
#define SB_OFF (4*SA_STG)              // 20480
#define SB_STG (HQB*NB*BPITCH)         // 3840
#define SINVA_OFF (SB_OFF + 4*SB_STG)  // 35840
#define SINVB_OFF (SINVA_OFF + 256)
#define SMEM_FLOATS (SINVB_OFF + HQB*NB)
#define SMEM_BYTES (SMEM_FLOATS*4)     // ~145KB

typedef unsigned int u32;

__device__ __forceinline__ unsigned smem_u32(const void* p) {
    return (unsigned)__cvta_generic_to_shared(p);
}
__device__ __forceinline__ u32 cvt_tf32(float v) {
    u32 r; asm("cvt.rna.tf32.f32 %0, %1;" : "=r"(r) : "f"(v)); return r;
}
__device__ __forceinline__ void mma_tf32(float c[4], const u32 a[4], const u32 b[2]) {
    asm volatile(
        "mma.sync.aligned.m16n8k8.row.col.f32.tf32.tf32.f32 "
        "{%0,%1,%2,%3}, {%4,%5,%6,%7}, {%8,%9}, {%0,%1,%2,%3};"
        : "+f"(c[0]), "+f"(c[1]), "+f"(c[2]), "+f"(c[3])
        : "r"(a[0]), "r"(a[1]), "r"(a[2]), "r"(a[3]), "r"(b[0]), "r"(b[1]));
}
__device__ __forceinline__ void ldm_x4(u32 r[4], unsigned addr) {
    asm volatile("ldmatrix.sync.aligned.m8n8.x4.shared.b16 {%0,%1,%2,%3}, [%4];"
                 : "=r"(r[0]), "=r"(r[1]), "=r"(r[2]), "=r"(r[3]) : "r"(addr));
}
__device__ __forceinline__ void ldm_x2(u32 r[2], unsigned addr) {
    asm volatile("ldmatrix.sync.aligned.m8n8.x2.shared.b16 {%0,%1}, [%2];"
                 : "=r"(r[0]), "=r"(r[1]) : "r"(addr));
}

__global__ __launch_bounds__(NTHREADS, 1)
void corr_mma_kernel(const float* __restrict__ fr, const float* __restrict__ fq,
                     float* __restrict__ out) {
    extern __shared__ float sm[];
    const int tid  = threadIdx.x;
    const int wid  = tid >> 5;
    const int lane = tid & 31;

    const int b   = blockIdx.z;
    const int hq0 = blockIdx.y * HQB;
    const int w0  = blockIdx.x * WT;

    // ---- structural-zero outputs (OOB fq rows): edge CTAs only (validated)
    {
        const int pd[10] = {0,0,0,0,1,1,1,2,2,3};
        const int ph[10] = {0,1,2,3,0,1,2,0,1,0};
        if (blockIdx.y == 0) {
            for (int idx = tid; idx < 1440; idx += NTHREADS) {
                int p = idx / 144, rem = idx % 144, dx = rem / 16, w = rem % 16;
                out[((size_t)b * 81 + pd[p] * ND + dx) * HWSZ + ph[p] * WW + w0 + w] = 0.f;
            }
        }
        if (blockIdx.y == (HH / HQB) - 1) {
            for (int idx = tid; idx < 1440; idx += NTHREADS) {
                int p = idx / 144, rem = idx % 144, dx = rem / 16, w = rem % 16;
                out[((size_t)b * 81 + (8 - pd[p]) * ND + dx) * HWSZ
                    + (HH - 1 - ph[p]) * WW + w0 + w] = 0.f;
            }
        }
    }

    // ---- A staging role
    const int apx = tid & 15;
    const int alh = tid >> 4;
    const int ah  = hq0 - 4 + alh;
    const bool av = (ah >= 0 && ah < HH);
    const float* aptr = fr + (size_t)b * CC * HWSZ + (av ? ah : 0) * WW + (w0 + apx);

    // ---- B staging role
    const int bpx = (tid < 192) ? (tid % NB) : 0;
    const int bhq = (tid < 192) ? (tid / NB) : 0;
    const int wq  = w0 - RD + bpx;
    const bool bv = (tid < 192) && (wq >= 0 && wq < WW);
    const float* bptr = fq + (size_t)b * CC * HWSZ + (hq0 + bhq) * WW + (bv ? wq : 0);

    float anrm = 0.f, bnrm = 0.f;
    float cAcc[27][4];
    #pragma unroll
    for (int i = 0; i < 27; ++i)
        #pragma unroll
        for (int j = 0; j < 4; ++j) cAcc[i][j] = 0.f;

    float avr[KC], bvr[KC];

    #define LDGSTAGE(S) do {                                                 \
        const size_t coff = (size_t)(S) * KC * HWSZ;                         \
        _Pragma("unroll")                                                    \
        for (int kc = 0; kc < KC; ++kc)                                      \
            avr[kc] = av ? aptr[coff + (size_t)kc * HWSZ] : 0.f;             \
        _Pragma("unroll")                                                    \
        for (int kc = 0; kc < KC; ++kc)                                      \
            bvr[kc] = bv ? bptr[coff + (size_t)kc * HWSZ] : 0.f;             \
    } while (0)

    #define STSSTAGE(BUF) do {                                               \
        _Pragma("unroll")                                                    \
        for (int kc = 0; kc < KC; ++kc) anrm = fmaf(avr[kc], avr[kc], anrm); \
        uint4* pa = (uint4*)(sm + (BUF) * SA_STG + (alh * 16 + apx) * APITCH);\
        pa[0] = make_uint4(cvt_tf32(avr[0]), cvt_tf32(avr[1]),               \
                           cvt_tf32(avr[2]), cvt_tf32(avr[3]));              \
        pa[1] = make_uint4(cvt_tf32(avr[4]), cvt_tf32(avr[5]),               \
                           cvt_tf32(avr[6]), cvt_tf32(avr[7]));              \
        pa[2] = make_uint4(cvt_tf32(avr[8]), cvt_tf32(avr[9]),               \
                           cvt_tf32(avr[10]), cvt_tf32(avr[11]));            \
        pa[3] = make_uint4(cvt_tf32(avr[12]), cvt_tf32(avr[13]),             \
                           cvt_tf32(avr[14]), cvt_tf32(avr[15]));            \
        if (tid < 192) {                                                     \
            _Pragma("unroll")                                                \
            for (int kc = 0; kc < KC; ++kc)                                  \
                bnrm = fmaf(bvr[kc], bvr[kc], bnrm);                         \
            uint4* pb = (uint4*)(sm + SB_OFF + (BUF) * SB_STG                \
                                 + (bhq * NB + bpx) * BPITCH);               \
            pb[0] = make_uint4(cvt_tf32(bvr[0]), cvt_tf32(bvr[1]),           \
                               cvt_tf32(bvr[2]), cvt_tf32(bvr[3]));          \
            pb[1] = make_uint4(cvt_tf32(bvr[4]), cvt_tf32(bvr[5]),           \
                               cvt_tf32(bvr[6]), cvt_tf32(bvr[7]));          \
            pb[2] = make_uint4(cvt_tf32(bvr[8]), cvt_tf32(bvr[9]),           \
                               cvt_tf32(bvr[10]), cvt_tf32(bvr[11]));        \
            pb[3] = make_uint4(cvt_tf32(bvr[12]), cvt_tf32(bvr[13]),         \
                               cvt_tf32(bvr[14]), cvt_tf32(bvr[15]));        \
        }                                                                    \
    } while (0)

    #define KSTEP(BUF, KS) do {                                              \
        u32 bF[3][2];                                                        \
        _Pragma("unroll")                                                    \
        for (int nt = 0; nt < 3; ++nt) {                                     \
            unsigned bd = smem_u32(sm + SB_OFF + (BUF) * SB_STG              \
                + (wid * NB + nt * 8 + (lane & 7)) * BPITCH                  \
                + (KS) * 8 + (((lane >> 3) & 1) << 2));                      \
            ldm_x2(bF[nt], bd);                                              \
        }                                                                    \
        _Pragma("unroll")                                                    \
        for (int dyt = 0; dyt < 9; ++dyt) {                                  \
            const int lh = wid + 8 - dyt;                                    \
            u32 aF[4];                                                       \
            unsigned ad = smem_u32(sm + (BUF) * SA_STG                       \
                + (lh * 16 + (lane & 15)) * APITCH                           \
                + (KS) * 8 + ((lane >> 4) << 2));                            \
            ldm_x4(aF, ad);                                                  \
            mma_tf32(cAcc[dyt * 3 + 0], aF, bF[0]);                          \
            mma_tf32(cAcc[dyt * 3 + 1], aF, bF[1]);                          \
            mma_tf32(cAcc[dyt * 3 + 2], aF, bF[2]);                          \
        }                                                                    \
    } while (0)

    // one barrier per TWO stages: process pair {P0,P1}, fill pair {W0,W1}
    #define PAIR(S0, P0, P1, W0, W1) do {                                    \
        if ((S0) + 2 < NSTG) LDGSTAGE((S0) + 2);                             \
        KSTEP(P0, 0);                                                        \
        KSTEP(P0, 1);                                                        \
        if ((S0) + 2 < NSTG) STSSTAGE(W0);                                   \
        if ((S0) + 3 < NSTG) LDGSTAGE((S0) + 3);                             \
        KSTEP(P1, 0);                                                        \
        KSTEP(P1, 1);                                                        \
        if ((S0) + 3 < NSTG) STSSTAGE(W1);                                   \
        __syncthreads();                                                     \
    } while (0)

    // ---- prologue: stages 0,1 -> bufs 0,1
    LDGSTAGE(0);
    STSSTAGE(0);
    LDGSTAGE(1);
    STSSTAGE(1);
    __syncthreads();

    #pragma unroll 1
    for (int q = 0; q < 4; ++q) {
        PAIR(4 * q + 0, 0, 1, 2, 3);
        PAIR(4 * q + 2, 2, 3, 0, 1);
    }

    // ---- norms to smem
    sm[SINVA_OFF + alh * 16 + apx] = 1.0f / fmaxf(sqrtf(anrm), 1e-12f);
    if (tid < 192)
        sm[SINVB_OFF + bhq * NB + bpx] = 1.0f / fmaxf(sqrtf(bnrm), 1e-12f);
    __syncthreads();

    // ---- epilogue (validated mapping)
    const float scale = 1.0f / (float)CC;
    const int r1 = lane >> 2;
    const int colb = 2 * (lane & 3);

    #pragma unroll
    for (int dyt = 0; dyt < 9; ++dyt) {
        const int h = hq0 + wid + 4 - dyt;
        if (h < 0 || h >= HH) continue;
        const int lh = wid + 8 - dyt;
        const float ia1 = sm[SINVA_OFF + lh * 16 + r1] * scale;
        const float ia2 = sm[SINVA_OFF + lh * 16 + r1 + 8] * scale;
        #pragma unroll
        for (int nt = 0; nt < 3; ++nt) {
            const int col0 = nt * 8 + colb;
            const float ib0 = sm[SINVB_OFF + wid * NB + col0];
            const float ib1 = sm[SINVB_OFF + wid * NB + col0 + 1];
            const float* cf = cAcc[dyt * 3 + nt];
            int dx;
            size_t pbase = ((size_t)b * 81 + dyt * ND) * HWSZ + h * WW + w0;
            dx = col0 - r1;
            if (dx >= 0 && dx < ND) out[pbase + (size_t)dx * HWSZ + r1] = cf[0] * ia1 * ib0;
            dx = col0 + 1 - r1;
            if (dx >= 0 && dx < ND) out[pbase + (size_t)dx * HWSZ + r1] = cf[1] * ia1 * ib1;
            dx = col0 - (r1 + 8);
            if (dx >= 0 && dx < ND) out[pbase + (size_t)dx * HWSZ + r1 + 8] = cf[2] * ia2 * ib0;
            dx = col0 + 1 - (r1 + 8);
            if (dx >= 0 && dx < ND) out[pbase + (size_t)dx * HWSZ + r1 + 8] = cf[3] * ia2 * ib1;
        }
    }
    #undef LDGSTAGE
    #undef STSSTAGE
    #undef KSTEP
    #undef PAIR
}

extern "C" void kernel_launch(void* const* d_in, const int* in_sizes, int n_in,
                              void* d_out, int out_size) {
    const float* fr = (const float*)d_in[0];
    const float* fq = (const float*)d_in[1];
    float* out = (float*)d_out;
    (void)in_sizes; (void)n_in; (void)out_size;

    cudaFuncSetAttribute(corr_mma_kernel,
                         cudaFuncAttributeMaxDynamicSharedMemorySize, SMEM_BYTES);

    dim3 grid(WW / WT, HH / HQB, BB);   // (8, 12, 8) = 768 CTAs
    corr_mma_kernel<<<grid, NTHREADS, SMEM_BYTES>>>(fr, fq, out);
}